// round 1
// baseline (speedup 1.0000x reference)
#include <cuda_runtime.h>
#include <cuda_bf16.h>
#include <cstdint>

#define BATCH 4
#define CIN   64
#define COUT  64
#define HW    224
#define KK    9
#define NBINS 10

#define TW 16      // output tile width
#define TH 8       // output tile height
#define CCH 8      // cin chunk

#define TILES_X (HW / TW)   // 14
#define TILES_Y (HW / TH)   // 28
#define NBLOCKS (BATCH * TILES_X * TILES_Y)   // 1568

#define Y_ELEMS (BATCH * COUT * HW * HW)      // 12,845,056

// Scratch (no device mallocs allowed)
__device__ float g_wT[CIN * KK * COUT];       // [ci][kk][co]
__device__ int   g_hist_i[CIN * NBINS];

// ---------------------------------------------------------------------------
// Weight transpose: w[co][ci][kh][kw] -> g_wT[ci][kk][co] (coalesced smem loads later)
// ---------------------------------------------------------------------------
__global__ void transpose_w_kernel(const float* __restrict__ w) {
    int t = blockIdx.x * blockDim.x + threadIdx.x;
    if (t < CIN * KK * COUT) {
        int co = t % COUT;
        int kk = (t / COUT) % KK;
        int ci = t / (COUT * KK);
        g_wT[t] = w[co * (CIN * KK) + ci * KK + kk];
    }
}

// ---------------------------------------------------------------------------
// Direct conv, GEMM-style register blocking.
// Block: 64 couts x 128 pixels (16x8). 256 threads.
//   warp w = cout group (8 couts, contiguous), lane -> pixel (4 pixels/thread).
// ---------------------------------------------------------------------------
__global__ __launch_bounds__(256, 3)
void conv_kernel(const float* __restrict__ x,
                 const float* __restrict__ bias,
                 float* __restrict__ y) {
    __shared__ float sx[CCH][TH + 2][TW + 2];   // 8*10*18*4 = 5760 B
    __shared__ float sw[CCH][KK][COUT];          // 8*9*64*4  = 18432 B

    const int bid = blockIdx.x;
    const int tx  = bid % TILES_X;
    const int ty  = (bid / TILES_X) % TILES_Y;
    const int b   = bid / (TILES_X * TILES_Y);
    const int wx0 = tx * TW;
    const int hy0 = ty * TH;

    const int tid   = threadIdx.x;
    const int cg    = tid >> 5;        // cout group 0..7
    const int lane  = tid & 31;
    const int pcol  = lane & 15;       // pixel col within tile
    const int prow0 = lane >> 4;       // 0/1; pixel rows are prow0 + 2*j

    float acc[8][4];
    #pragma unroll
    for (int i = 0; i < 8; i++)
        #pragma unroll
        for (int j = 0; j < 4; j++) acc[i][j] = 0.0f;

    for (int c0 = 0; c0 < CIN; c0 += CCH) {
        // --- load x tile (with zero padding) ---
        #pragma unroll
        for (int i = tid; i < CCH * (TH + 2) * (TW + 2); i += 256) {
            int col = i % (TW + 2);
            int row = (i / (TW + 2)) % (TH + 2);
            int ci  = i / ((TW + 2) * (TH + 2));
            int gx = wx0 + col - 1;
            int gy = hy0 + row - 1;
            float v = 0.0f;
            if (gx >= 0 && gx < HW && gy >= 0 && gy < HW)
                v = __ldg(&x[((size_t)(b * CIN + c0 + ci) * HW + gy) * HW + gx]);
            sx[ci][row][col] = v;
        }
        // --- load weight chunk (contiguous copy) ---
        {
            const float* wsrc = g_wT + (size_t)c0 * KK * COUT;
            float* wdst = &sw[0][0][0];
            #pragma unroll
            for (int i = tid; i < CCH * KK * COUT; i += 256)
                wdst[i] = wsrc[i];
        }
        __syncthreads();

        for (int ci = 0; ci < CCH; ci++) {
            #pragma unroll
            for (int kh = 0; kh < 3; kh++) {
                #pragma unroll
                for (int kw = 0; kw < 3; kw++) {
                    float xv[4];
                    #pragma unroll
                    for (int j = 0; j < 4; j++)
                        xv[j] = sx[ci][prow0 + 2 * j + kh][pcol + kw];
                    const float* wp = &sw[ci][kh * 3 + kw][cg * 8];
                    float4 w0 = *reinterpret_cast<const float4*>(wp);
                    float4 w1 = *reinterpret_cast<const float4*>(wp + 4);
                    float wv[8] = {w0.x, w0.y, w0.z, w0.w, w1.x, w1.y, w1.z, w1.w};
                    #pragma unroll
                    for (int co = 0; co < 8; co++)
                        #pragma unroll
                        for (int j = 0; j < 4; j++)
                            acc[co][j] = fmaf(wv[co], xv[j], acc[co][j]);
                }
            }
        }
        __syncthreads();
    }

    // --- epilogue: + bias, store ---
    #pragma unroll
    for (int co = 0; co < 8; co++) {
        int oc = cg * 8 + co;
        float bv = __ldg(&bias[oc]);
        #pragma unroll
        for (int j = 0; j < 4; j++) {
            int gy = hy0 + prow0 + 2 * j;
            int gx = wx0 + pcol;
            y[((size_t)(b * COUT + oc) * HW + gy) * HW + gx] = acc[co][j] + bv;
        }
    }
}

// ---------------------------------------------------------------------------
// Histogram of per-window zero counts (exact semantics):
// product(b,c,ho,wo,kk) == 0  iff  padding || x==0 || weight[0,c,kk]==0
// ---------------------------------------------------------------------------
__global__ void hist_zero_kernel() {
    int t = threadIdx.x;
    if (t < CIN * NBINS) g_hist_i[t] = 0;
}

#define HROWS 8
#define HCHUNKS (HW / HROWS)   // 28

__global__ __launch_bounds__(256)
void hist_count_kernel(const float* __restrict__ x, const float* __restrict__ w) {
    int bz = blockIdx.x;
    int rc = bz % HCHUNKS;
    int c  = (bz / HCHUNKS) % CIN;
    int b  = bz / (HCHUNKS * CIN);

    bool wz[KK];
    #pragma unroll
    for (int k = 0; k < KK; k++) wz[k] = (__ldg(&w[c * KK + k]) == 0.0f);

    const float* xp = x + (size_t)(b * CIN + c) * (HW * HW);

    int cnt[NBINS];
    #pragma unroll
    for (int i = 0; i < NBINS; i++) cnt[i] = 0;

    int hy0 = rc * HROWS;
    #pragma unroll
    for (int it = 0; it < (HROWS * HW) / 256; it++) {   // 7 iters
        int p   = threadIdx.x + it * 256;
        int row = hy0 + (p / HW);
        int col = p % HW;
        int z = 0;
        #pragma unroll
        for (int kh = 0; kh < 3; kh++) {
            #pragma unroll
            for (int kw = 0; kw < 3; kw++) {
                int gy = row + kh - 1;
                int gx = col + kw - 1;
                bool zero;
                if (gy < 0 || gy >= HW || gx < 0 || gx >= HW) {
                    zero = true;
                } else {
                    zero = wz[kh * 3 + kw] || (__ldg(&xp[gy * HW + gx]) == 0.0f);
                }
                z += zero ? 1 : 0;
            }
        }
        #pragma unroll
        for (int bin = 0; bin < NBINS; bin++) cnt[bin] += (z == bin) ? 1 : 0;
    }

    __shared__ int sh[NBINS];
    if (threadIdx.x < NBINS) sh[threadIdx.x] = 0;
    __syncthreads();
    #pragma unroll
    for (int bin = 0; bin < NBINS; bin++) {
        int v = cnt[bin];
        #pragma unroll
        for (int o = 16; o > 0; o >>= 1) v += __shfl_down_sync(0xFFFFFFFFu, v, o);
        if ((threadIdx.x & 31) == 0 && v) atomicAdd(&sh[bin], v);
    }
    __syncthreads();
    if (threadIdx.x < NBINS && sh[threadIdx.x])
        atomicAdd(&g_hist_i[c * NBINS + threadIdx.x], sh[threadIdx.x]);
}

__global__ void hist_write_kernel(float* __restrict__ out_hist) {
    int t = threadIdx.x;
    if (t < CIN * NBINS) out_hist[t] = (float)g_hist_i[t];
}

// ---------------------------------------------------------------------------
extern "C" void kernel_launch(void* const* d_in, const int* in_sizes, int n_in,
                              void* d_out, int out_size) {
    const float* x    = (const float*)d_in[0];   // (4,64,224,224)
    const float* wgt  = (const float*)d_in[1];   // (64,64,3,3)
    const float* bias = (const float*)d_in[2];   // (64,)
    float* y    = (float*)d_out;                 // y then hist, flattened
    float* hist = (float*)d_out + (size_t)Y_ELEMS;

    transpose_w_kernel<<<(CIN * KK * COUT + 255) / 256, 256>>>(wgt);
    conv_kernel<<<NBLOCKS, 256>>>(x, bias, y);
    hist_zero_kernel<<<1, CIN * NBINS>>>();
    hist_count_kernel<<<BATCH * CIN * HCHUNKS, 256>>>(x, wgt);
    hist_write_kernel<<<1, CIN * NBINS>>>(hist);
}

// round 2
// speedup vs baseline: 1.2000x; 1.2000x over previous
#include <cuda_runtime.h>
#include <cuda_bf16.h>
#include <cstdint>

#define BATCH 4
#define CIN   64
#define COUT  64
#define HW    224
#define KK    9
#define NBINS 10

#define TW 16      // output tile width
#define TH 8       // output tile height
#define CCH 8      // cin chunk

#define TILES_X (HW / TW)   // 14
#define TILES_Y (HW / TH)   // 28
#define NBLOCKS (BATCH * TILES_X * TILES_Y)   // 1568

#define Y_ELEMS (BATCH * COUT * HW * HW)      // 12,845,056

typedef unsigned long long ull;

#define FMA_F32X2(d, a, b, c) \
    asm("fma.rn.f32x2 %0, %1, %2, %3;" : "=l"(d) : "l"(a), "l"(b), "l"(c))
#define PACK_F32X2(out, lo, hi) \
    asm("mov.b64 %0, {%1, %2};" : "=l"(out) : "f"(lo), "f"(hi))
#define UNPACK_F32X2(lo, hi, in) \
    asm("mov.b64 {%0, %1}, %2;" : "=f"(lo), "=f"(hi) : "l"(in))

// Scratch (no device mallocs allowed)
__device__ float g_wT[CIN * KK * COUT];       // [ci][kk][co]
__device__ int   g_hist_i[CIN * NBINS];

// ---------------------------------------------------------------------------
// Weight transpose: w[co][ci][kh][kw] -> g_wT[ci][kk][co]
// ---------------------------------------------------------------------------
__global__ void transpose_w_kernel(const float* __restrict__ w) {
    int t = blockIdx.x * blockDim.x + threadIdx.x;
    if (t < CIN * KK * COUT) {
        int co = t % COUT;
        int kk = (t / COUT) % KK;
        int ci = t / (COUT * KK);
        g_wT[t] = w[co * (CIN * KK) + ci * KK + kk];
    }
}

// ---------------------------------------------------------------------------
// Direct conv, GEMM-style register blocking, packed f32x2 math.
// Block: 64 couts x 128 pixels (16x8). 256 threads.
//   warp = cout group (8 couts = 4 f32x2 pairs), lane -> pixel (4 pixels).
// ---------------------------------------------------------------------------
__global__ __launch_bounds__(256, 3)
void conv_kernel(const float* __restrict__ x,
                 const float* __restrict__ bias,
                 float* __restrict__ y) {
    __shared__ __align__(16) float sx[CCH][TH + 2][TW + 2];   // 5760 B
    __shared__ __align__(16) float sw[CCH][KK][COUT];          // 18432 B

    const int bid = blockIdx.x;
    const int tx  = bid % TILES_X;
    const int ty  = (bid / TILES_X) % TILES_Y;
    const int b   = bid / (TILES_X * TILES_Y);
    const int wx0 = tx * TW;
    const int hy0 = ty * TH;

    const int tid   = threadIdx.x;
    const int cg    = tid >> 5;        // cout group 0..7
    const int lane  = tid & 31;
    const int pcol  = lane & 15;       // pixel col within tile
    const int prow0 = lane >> 4;       // 0/1; pixel rows: prow0 + 2*j

    // acc2[cp][j]: f32x2 pair = couts (cg*8+2cp, cg*8+2cp+1) at pixel j
    ull acc2[4][4];
    #pragma unroll
    for (int i = 0; i < 4; i++)
        #pragma unroll
        for (int j = 0; j < 4; j++) acc2[i][j] = 0ULL;

    for (int c0 = 0; c0 < CIN; c0 += CCH) {
        // --- load x tile (with zero padding) ---
        #pragma unroll
        for (int i = tid; i < CCH * (TH + 2) * (TW + 2); i += 256) {
            int col = i % (TW + 2);
            int row = (i / (TW + 2)) % (TH + 2);
            int ci  = i / ((TW + 2) * (TH + 2));
            int gx = wx0 + col - 1;
            int gy = hy0 + row - 1;
            float v = 0.0f;
            if (gx >= 0 && gx < HW && gy >= 0 && gy < HW)
                v = __ldg(&x[((size_t)(b * CIN + c0 + ci) * HW + gy) * HW + gx]);
            sx[ci][row][col] = v;
        }
        // --- load weight chunk (contiguous copy) ---
        {
            const float* wsrc = g_wT + (size_t)c0 * KK * COUT;
            float* wdst = &sw[0][0][0];
            #pragma unroll
            for (int i = tid; i < CCH * KK * COUT; i += 256)
                wdst[i] = wsrc[i];
        }
        __syncthreads();

        for (int ci = 0; ci < CCH; ci++) {
            #pragma unroll
            for (int kh = 0; kh < 3; kh++) {
                #pragma unroll
                for (int kw = 0; kw < 3; kw++) {
                    ull xx[4];
                    #pragma unroll
                    for (int j = 0; j < 4; j++) {
                        float xv = sx[ci][prow0 + 2 * j + kh][pcol + kw];
                        PACK_F32X2(xx[j], xv, xv);
                    }
                    const ull* wp = reinterpret_cast<const ull*>(
                        &sw[ci][kh * 3 + kw][cg * 8]);
                    ull w2[4];
                    #pragma unroll
                    for (int cp = 0; cp < 4; cp++) w2[cp] = wp[cp];
                    #pragma unroll
                    for (int cp = 0; cp < 4; cp++)
                        #pragma unroll
                        for (int j = 0; j < 4; j++)
                            FMA_F32X2(acc2[cp][j], w2[cp], xx[j], acc2[cp][j]);
                }
            }
        }
        __syncthreads();
    }

    // --- epilogue: + bias, store ---
    #pragma unroll
    for (int cp = 0; cp < 4; cp++) {
        int oc0 = cg * 8 + 2 * cp;
        float b0 = __ldg(&bias[oc0]);
        float b1 = __ldg(&bias[oc0 + 1]);
        #pragma unroll
        for (int j = 0; j < 4; j++) {
            int gy = hy0 + prow0 + 2 * j;
            int gx = wx0 + pcol;
            float lo, hi;
            UNPACK_F32X2(lo, hi, acc2[cp][j]);
            y[((size_t)(b * COUT + oc0)     * HW + gy) * HW + gx] = lo + b0;
            y[((size_t)(b * COUT + oc0 + 1) * HW + gy) * HW + gx] = hi + b1;
        }
    }
}

// ---------------------------------------------------------------------------
// Histogram of per-window zero counts.
// product(b,c,ho,wo,k) == 0  iff  pad || x==0 || weight[0,c,k]==0
// Fast path (no weight exactly 0): z = separable 3x3 window sum of
//   u(pixel) = pad || (x==0).
// ---------------------------------------------------------------------------
__global__ void hist_zero_kernel() {
    int t = threadIdx.x;
    if (t < CIN * NBINS) g_hist_i[t] = 0;
}

#define HCH 4                 // row chunks per image plane
#define HROWS (HW / HCH)      // 56

__global__ __launch_bounds__(256)
void hist_count_kernel(const float* __restrict__ x, const float* __restrict__ w) {
    const int bz = blockIdx.x;
    const int rc = bz % HCH;
    const int c  = (bz / HCH) % CIN;
    const int b  = bz / (HCH * CIN);
    const int r0 = rc * HROWS;

    const int tid = threadIdx.x;
    const int col = tid;
    const bool active = (col < HW);

    __shared__ int su[HW + 2];
    __shared__ int sbin[NBINS];

    bool wz[KK];
    bool anywz = false;
    #pragma unroll
    for (int k = 0; k < KK; k++) {
        wz[k] = (__ldg(&w[c * KK + k]) == 0.0f);
        anywz |= wz[k];
    }

    if (tid < NBINS) sbin[tid] = 0;
    if (tid == 0) { su[0] = 1; su[HW + 1] = 1; }
    __syncthreads();

    const float* xp = x + (size_t)(b * CIN + c) * (HW * HW);

    if (!anywz) {
        // ---- fast separable path ----
        int cnt0 = 0;

        auto fetch = [&](int row) -> float {
            return (row >= 0 && row < HW && active) ? __ldg(&xp[row * HW + col])
                                                    : 1.0f;
        };
        auto use_r = [&](int row, float xv) -> int {
            if (row < 0 || row >= HW) return 3;   // uniform condition
            __syncthreads();
            if (active) su[col + 1] = (xv == 0.0f) ? 1 : 0;
            __syncthreads();
            return active ? su[col] + su[col + 1] + su[col + 2] : 0;
        };

        float xb = fetch(r0 - 1);
        float xc = fetch(r0);
        float xn = fetch(r0 + 1);
        int r_prev = use_r(r0 - 1, xb);
        int r_cur  = use_r(r0, xc);

        for (int row = r0; row < r0 + HROWS; row++) {
            float xd = fetch(row + 2);            // 2-row-ahead prefetch
            int r_next = use_r(row + 1, xn);
            if (active) {
                int z = r_prev + r_cur + r_next;
                if (z == 0) cnt0++;
                else atomicAdd(&sbin[z], 1);
            }
            r_prev = r_cur; r_cur = r_next; xn = xd;
        }
        if (active && cnt0) atomicAdd(&sbin[0], cnt0);
    } else {
        // ---- exact fallback (any weight of out-channel 0 exactly zero) ----
        for (int row = r0; row < r0 + HROWS; row++) {
            if (active) {
                int z = 0;
                #pragma unroll
                for (int kh = 0; kh < 3; kh++) {
                    #pragma unroll
                    for (int kw = 0; kw < 3; kw++) {
                        int gy = row + kh - 1;
                        int gx = col + kw - 1;
                        bool zero;
                        if (gy < 0 || gy >= HW || gx < 0 || gx >= HW)
                            zero = true;
                        else
                            zero = wz[kh * 3 + kw] ||
                                   (__ldg(&xp[gy * HW + gx]) == 0.0f);
                        z += zero ? 1 : 0;
                    }
                }
                atomicAdd(&sbin[z], 1);
            }
        }
    }

    __syncthreads();
    if (tid < NBINS && sbin[tid])
        atomicAdd(&g_hist_i[c * NBINS + tid], sbin[tid]);
}

__global__ void hist_write_kernel(float* __restrict__ out_hist) {
    int t = threadIdx.x;
    if (t < CIN * NBINS) out_hist[t] = (float)g_hist_i[t];
}

// ---------------------------------------------------------------------------
extern "C" void kernel_launch(void* const* d_in, const int* in_sizes, int n_in,
                              void* d_out, int out_size) {
    const float* x    = (const float*)d_in[0];   // (4,64,224,224)
    const float* wgt  = (const float*)d_in[1];   // (64,64,3,3)
    const float* bias = (const float*)d_in[2];   // (64,)
    float* y    = (float*)d_out;
    float* hist = (float*)d_out + (size_t)Y_ELEMS;

    transpose_w_kernel<<<(CIN * KK * COUT + 255) / 256, 256>>>(wgt);
    conv_kernel<<<NBLOCKS, 256>>>(x, bias, y);
    hist_zero_kernel<<<1, CIN * NBINS>>>();
    hist_count_kernel<<<BATCH * CIN * HCH, 256>>>(x, wgt);
    hist_write_kernel<<<1, CIN * NBINS>>>(hist);
}

// round 4
// speedup vs baseline: 2.1559x; 1.7965x over previous
#include <cuda_runtime.h>
#include <cstdint>

#define BATCH 4
#define CIN   64
#define COUT  64
#define HW    224
#define NPIX  (HW * HW)          // 50176
#define KK    9
#define NBINS 10
#define KTOT  (CIN * KK)         // 576
#define KC    32
#define NCHUNK (KTOT / KC)       // 18
#define TILE_M 128
#define NTILE (NPIX / TILE_M)    // 392
#define NBLOCKS (BATCH * NTILE)  // 1568
#define Y_ELEMS (BATCH * COUT * NPIX)

// B fragments, tf32 bits, layout [chunk][nt 8][ks 4][lane 32][2]
__device__ uint32_t g_wfrag[NCHUNK * 2048];
__device__ int g_hist_i[CIN * NBINS];

__device__ __forceinline__ uint32_t f2tf32(float v) {
    uint32_t u;
    asm("cvt.rna.tf32.f32 %0, %1;" : "=r"(u) : "f"(v));
    return u;
}

#define MMA_TF32(d, a, b) \
    asm volatile("mma.sync.aligned.m16n8k8.row.col.f32.tf32.tf32.f32 " \
        "{%0,%1,%2,%3}, {%4,%5,%6,%7}, {%8,%9}, {%0,%1,%2,%3};" \
        : "+f"((d)[0]), "+f"((d)[1]), "+f"((d)[2]), "+f"((d)[3]) \
        : "r"((a).x), "r"((a).y), "r"((a).z), "r"((a).w), \
          "r"((b).x), "r"((b).y))

// ---------------------------------------------------------------------------
// Repack W (64, 576) -> fragment order, tf32-rounded.
// idx = ((((c*8 + nt)*4 + ks)*32) + lane)*2 + pair
//   n = nt*8 + (lane>>2);  k = c*32 + ks*8 + (lane&3) + pair*4
// ---------------------------------------------------------------------------
__global__ void repack_w_kernel(const float* __restrict__ w) {
    int idx = blockIdx.x * blockDim.x + threadIdx.x;
    if (idx < NCHUNK * 2048) {
        int pair = idx & 1;
        int lane = (idx >> 1) & 31;
        int ks   = (idx >> 6) & 3;
        int nt   = (idx >> 8) & 7;
        int c    = idx >> 11;
        int n = nt * 8 + (lane >> 2);
        int k = c * 32 + ks * 8 + (lane & 3) + pair * 4;
        g_wfrag[idx] = f2tf32(__ldg(&w[n * KTOT + k]));
    }
}

// ---------------------------------------------------------------------------
// Implicit-GEMM conv via mma.sync tf32 (m16n8k8).
// CTA: 128 pixels x 64 couts. 8 warps: (w&3) -> M block of 32, (w>>2) -> N 32.
// ---------------------------------------------------------------------------
__global__ __launch_bounds__(256, 2)
void conv_mma_kernel(const float* __restrict__ x,
                     const float* __restrict__ bias,
                     float* __restrict__ y) {
    __shared__ __align__(16) uint32_t sA[2][4096];   // 2 x 16KB frag-order A
    __shared__ int   tab[KTOT];
    __shared__ float sbias[COUT];

    const int tid = threadIdx.x;

    for (int i = tid; i < KTOT; i += 256) {
        int ci = i / 9, tap = i - ci * 9;
        int dh = tap / 3, dw = tap - dh * 3;        // 0..2
        int off = ci * NPIX + (dh - 1) * HW + (dw - 1) + (HW + 1);
        tab[i] = off | (dh << 24) | (dw << 26);
    }
    if (tid < COUT) sbias[tid] = __ldg(&bias[tid]);

    const int b    = blockIdx.x / NTILE;
    const int pix0 = (blockIdx.x % NTILE) * TILE_M;
    const float* xb = x + (size_t)b * CIN * NPIX;

    // ---- writer slot state (4 slots: m tiles mtb, mtb+2, mtb+4, mtb+6) ----
    const int lane_s = tid & 31;
    const int ks_s   = (tid >> 5) & 3;
    const int g_s    = lane_s >> 2;
    const int th_s   = lane_s & 3;
    const int kkoff  = ks_s * 8 + th_s;     // chunk-local k for a0/a1 (a2/a3: +4)
    const int mtb    = tid >> 7;            // 0/1

    const float* ptr[8];
    int msk[8];
    #pragma unroll
    for (int i = 0; i < 4; i++) {
        #pragma unroll
        for (int half = 0; half < 2; half++) {
            int m  = (mtb + 2 * i) * 16 + g_s + half * 8;
            int pm = pix0 + m;
            int hm = pm / HW, wm = pm - hm * HW;
            ptr[i * 2 + half] = xb + hm * HW + wm - (HW + 1);
            int mk = 2 | 16;                         // center row/col valid
            if (hm > 0)      mk |= 1;
            if (hm + 1 < HW) mk |= 4;
            if (wm > 0)      mk |= 8;
            if (wm + 1 < HW) mk |= 32;
            msk[i * 2 + half] = mk;
        }
    }
    const int base0 = ((mtb * 4 + ks_s) * 32 + lane_s) * 4;   // word offset

    __syncthreads();   // tab/sbias ready before first loadA

    uint32_t areg[4][4];
    auto loadA = [&](int c) {
        const int k0 = c * KC;
        const int ea = tab[k0 + kkoff];
        const int eb = tab[k0 + kkoff + 4];
        const int dah = (ea >> 24) & 3, daw = (ea >> 26) & 3;
        const int dbh = (eb >> 24) & 3, dbw = (eb >> 26) & 3;
        const int offa = ea & 0x3FFFFF, offb = eb & 0x3FFFFF;
        #pragma unroll
        for (int i = 0; i < 4; i++) {
            #pragma unroll
            for (int half = 0; half < 2; half++) {
                const int s = i * 2 + half;
                const int mkv = msk[s];
                const float* pp = ptr[s];
                bool oka = ((mkv >> dah) & (mkv >> (3 + daw)) & 1) != 0;
                bool okb = ((mkv >> dbh) & (mkv >> (3 + dbw)) & 1) != 0;
                float va = oka ? __ldg(pp + offa) : 0.0f;
                float vb = okb ? __ldg(pp + offb) : 0.0f;
                areg[i][half]     = f2tf32(va);   // a0 / a1
                areg[i][2 + half] = f2tf32(vb);   // a2 / a3
            }
        }
    };

    const int w    = tid >> 5;
    const int lane = tid & 31;
    const int wm2  = (w & 3) * 2;
    const int wn4  = (w >> 2) * 4;

    float d[2][4][4];
    #pragma unroll
    for (int mt = 0; mt < 2; mt++)
        #pragma unroll
        for (int nt = 0; nt < 4; nt++)
            #pragma unroll
            for (int k = 0; k < 4; k++) d[mt][nt][k] = 0.0f;

    loadA(0);
    for (int c = 0; c < NCHUNK; c++) {
        const int p = c & 1;
        #pragma unroll
        for (int i = 0; i < 4; i++)
            *(uint4*)&sA[p][base0 + i * 1024] =
                make_uint4(areg[i][0], areg[i][1], areg[i][2], areg[i][3]);
        __syncthreads();
        if (c + 1 < NCHUNK) loadA(c + 1);

        const uint2* bw = (const uint2*)g_wfrag + (size_t)(c * 8 + wn4) * 128;
        #pragma unroll
        for (int ks = 0; ks < 4; ks++) {
            uint4 a0 = *(const uint4*)&sA[p][((wm2 * 4 + ks) * 32 + lane) * 4];
            uint4 a1 = *(const uint4*)&sA[p][(((wm2 + 1) * 4 + ks) * 32 + lane) * 4];
            #pragma unroll
            for (int nt = 0; nt < 4; nt++) {
                uint2 bv = __ldg(&bw[(nt * 4 + ks) * 32 + lane]);
                MMA_TF32(d[0][nt], a0, bv);
                MMA_TF32(d[1][nt], a1, bv);
            }
        }
    }

    // ---- epilogue ----
    float* yb = y + (size_t)b * COUT * NPIX + pix0;
    const int rbase = (w & 3) * 32 + (lane >> 2);
    const int cbase = (w >> 2) * 32 + (lane & 3) * 2;
    #pragma unroll
    for (int mt = 0; mt < 2; mt++) {
        #pragma unroll
        for (int nt = 0; nt < 4; nt++) {
            int r0 = rbase + mt * 16;
            int c0 = cbase + nt * 8;
            float b0 = sbias[c0], b1 = sbias[c0 + 1];
            yb[(size_t)c0 * NPIX + r0]           = d[mt][nt][0] + b0;
            yb[(size_t)(c0 + 1) * NPIX + r0]     = d[mt][nt][1] + b1;
            yb[(size_t)c0 * NPIX + r0 + 8]       = d[mt][nt][2] + b0;
            yb[(size_t)(c0 + 1) * NPIX + r0 + 8] = d[mt][nt][3] + b1;
        }
    }
}

// ============================ histogram (round-2, passing) ============================
__global__ void hist_zero_kernel() {
    int t = threadIdx.x;
    if (t < CIN * NBINS) g_hist_i[t] = 0;
}

#define HCH 4
#define HROWS (HW / HCH)      // 56

__global__ __launch_bounds__(256)
void hist_count_kernel(const float* __restrict__ x, const float* __restrict__ w) {
    const int bz = blockIdx.x;
    const int rc = bz % HCH;
    const int c  = (bz / HCH) % CIN;
    const int b  = bz / (HCH * CIN);
    const int r0 = rc * HROWS;

    const int tid = threadIdx.x;
    const int col = tid;
    const bool active = (col < HW);

    __shared__ int su[HW + 2];
    __shared__ int sbin[NBINS];

    bool wz[KK];
    bool anywz = false;
    #pragma unroll
    for (int k = 0; k < KK; k++) {
        wz[k] = (__ldg(&w[c * KK + k]) == 0.0f);
        anywz |= wz[k];
    }

    if (tid < NBINS) sbin[tid] = 0;
    if (tid == 0) { su[0] = 1; su[HW + 1] = 1; }
    __syncthreads();

    const float* xp = x + (size_t)(b * CIN + c) * (HW * HW);

    if (!anywz) {
        int cnt0 = 0;

        auto fetch = [&](int row) -> float {
            return (row >= 0 && row < HW && active) ? __ldg(&xp[row * HW + col])
                                                    : 1.0f;
        };
        auto use_r = [&](int row, float xv) -> int {
            if (row < 0 || row >= HW) return 3;
            __syncthreads();
            if (active) su[col + 1] = (xv == 0.0f) ? 1 : 0;
            __syncthreads();
            return active ? su[col] + su[col + 1] + su[col + 2] : 0;
        };

        float xb = fetch(r0 - 1);
        float xc = fetch(r0);
        float xn = fetch(r0 + 1);
        int r_prev = use_r(r0 - 1, xb);
        int r_cur  = use_r(r0, xc);

        for (int row = r0; row < r0 + HROWS; row++) {
            float xd = fetch(row + 2);
            int r_next = use_r(row + 1, xn);
            if (active) {
                int z = r_prev + r_cur + r_next;
                if (z == 0) cnt0++;
                else atomicAdd(&sbin[z], 1);
            }
            r_prev = r_cur; r_cur = r_next; xn = xd;
        }
        if (active && cnt0) atomicAdd(&sbin[0], cnt0);
    } else {
        for (int row = r0; row < r0 + HROWS; row++) {
            if (active) {
                int z = 0;
                #pragma unroll
                for (int kh = 0; kh < 3; kh++) {
                    #pragma unroll
                    for (int kw = 0; kw < 3; kw++) {
                        int gy = row + kh - 1;
                        int gx = col + kw - 1;
                        bool zero;
                        if (gy < 0 || gy >= HW || gx < 0 || gx >= HW)
                            zero = true;
                        else
                            zero = wz[kh * 3 + kw] ||
                                   (__ldg(&xp[gy * HW + gx]) == 0.0f);
                        z += zero ? 1 : 0;
                    }
                }
                atomicAdd(&sbin[z], 1);
            }
        }
    }

    __syncthreads();
    if (tid < NBINS && sbin[tid])
        atomicAdd(&g_hist_i[c * NBINS + tid], sbin[tid]);
}

__global__ void hist_write_kernel(float* __restrict__ out_hist) {
    int t = threadIdx.x;
    if (t < CIN * NBINS) out_hist[t] = (float)g_hist_i[t];
}

// ---------------------------------------------------------------------------
extern "C" void kernel_launch(void* const* d_in, const int* in_sizes, int n_in,
                              void* d_out, int out_size) {
    const float* x    = (const float*)d_in[0];   // (4,64,224,224)
    const float* wgt  = (const float*)d_in[1];   // (64,64,3,3)
    const float* bias = (const float*)d_in[2];   // (64,)
    float* y    = (float*)d_out;
    float* hist = (float*)d_out + (size_t)Y_ELEMS;

    repack_w_kernel<<<(NCHUNK * 2048 + 255) / 256, 256>>>(wgt);
    conv_mma_kernel<<<NBLOCKS, 256>>>(x, bias, y);
    hist_zero_kernel<<<1, CIN * NBINS>>>();
    hist_count_kernel<<<BATCH * CIN * HCH, 256>>>(x, wgt);
    hist_write_kernel<<<1, CIN * NBINS>>>(hist);
}